// round 12
// baseline (speedup 1.0000x reference)
#include <cuda_runtime.h>
#include <cstdint>
#include <math.h>

// x [128, 1, 512, 512] fp32.
//   pred = softplus(x); m = max over sample; out = (m > 1e-8) ? pred/m : pred.
// softplus monotone => m = softplus(max(x)).
//
// R12: ALL prior designs plateaued at 57.6-57.9us because each moved 402 MB
// through L2 (read + re-read + write) against the ~6.9 TB/s LTS cap
// (402/6.9 = 58.3us -- matches every measurement). This version removes the
// 134 MB re-read from L2: a single persistent kernel stages each 32 KB chunk
// in SMEM, syncs per-sample via arrive counters + spin (co-resident grid =>
// deadlock-free), and does pass 2 from SMEM. L2 traffic = 268 MB -> ~39us
// floor. Counters self-reset (leave counter) so graph replays are clean.

#define SAMPLES 128
#define SAMPLE_ELEMS (512 * 512)            // 262144
#define CHUNKS 32                           // chunks per sample
#define CHUNK_ELEMS (SAMPLE_ELEMS / CHUNKS) // 8192 floats = 32 KB
#define CHUNK_N4 (CHUNK_ELEMS / 4)          // 2048 float4
#define THREADS 256                         // 8 float4 per thread
#define GRID 592                            // 148 SMs * 4 CTAs (co-resident)
#define SMEM_BYTES (CHUNK_N4 * 16)          // 32768
#define EPS 1e-8f
#define LOG2E 1.4426950408889634f
#define LN2   0.6931471805599453f

__device__ unsigned g_smax[SAMPLES];        // ordered-uint max; 0 = "empty"
__device__ unsigned g_arrive[SAMPLES];      // arrivals (0 at launch start/end)
__device__ unsigned g_leave[SAMPLES];       // departures

__device__ __forceinline__ unsigned ord_encode(float f) {
    unsigned u = __float_as_uint(f);
    return (u >> 31) ? ~u : (u | 0x80000000u);
}
__device__ __forceinline__ float ord_decode(unsigned u) {
    return __uint_as_float((u >> 31) ? (u ^ 0x80000000u) : ~u);
}

__device__ __forceinline__ float softplus_accurate(float x) {
    return fmaxf(x, 0.0f) + log1pf(__expf(-fabsf(x)));
}
__device__ __forceinline__ float ex2f(float x) {
    float r; asm("ex2.approx.ftz.f32 %0, %1;" : "=f"(r) : "f"(x)); return r;
}
__device__ __forceinline__ float lg2f(float x) {
    float r; asm("lg2.approx.ftz.f32 %0, %1;" : "=f"(r) : "f"(x)); return r;
}
__device__ __forceinline__ float softplus_scaled(float x, float scale, float scale_ln2) {
    float t = ex2f(-LOG2E * fabsf(x));      // e^(-|x|)
    float l = lg2f(1.0f + t);               // log2(1 + e^-|x|)
    return fmaf(scale, fmaxf(x, 0.0f), scale_ln2 * l);
}

__device__ __forceinline__ unsigned ld_acquire_gpu(const unsigned* p) {
    unsigned v;
    asm volatile("ld.acquire.gpu.u32 %0, [%1];" : "=r"(v) : "l"(p));
    return v;
}

__global__ __launch_bounds__(THREADS)
void persist_kernel(const float* __restrict__ x, float* __restrict__ out,
                    int total_work) {
    extern __shared__ float4 stage[];       // 2048 float4 = 32 KB
    __shared__ float s_red[THREADS / 32];
    __shared__ float s_scale;

    const int tid = threadIdx.x;

    for (int w = blockIdx.x; w < total_work; w += GRID) {
        const int sample = w >> 5;          // / CHUNKS
        const size_t off4 = (size_t)w * CHUNK_N4;
        const float4* __restrict__ xin = reinterpret_cast<const float4*>(x) + off4;
        float4* __restrict__ o = reinterpret_cast<float4*>(out) + off4;

        // ---- Pass 1: stream chunk -> SMEM, reduce chunk max ----
        float m0 = -INFINITY, m1 = -INFINITY, m2 = -INFINITY, m3 = -INFINITY;
        #pragma unroll
        for (int i = 0; i < 8; i += 4) {
            float4 a = __ldcs(&xin[(i + 0) * THREADS + tid]);
            float4 b = __ldcs(&xin[(i + 1) * THREADS + tid]);
            float4 c = __ldcs(&xin[(i + 2) * THREADS + tid]);
            float4 d = __ldcs(&xin[(i + 3) * THREADS + tid]);
            stage[(i + 0) * THREADS + tid] = a;
            stage[(i + 1) * THREADS + tid] = b;
            stage[(i + 2) * THREADS + tid] = c;
            stage[(i + 3) * THREADS + tid] = d;
            m0 = fmaxf(m0, fmaxf(fmaxf(a.x, a.y), fmaxf(a.z, a.w)));
            m1 = fmaxf(m1, fmaxf(fmaxf(b.x, b.y), fmaxf(b.z, b.w)));
            m2 = fmaxf(m2, fmaxf(fmaxf(c.x, c.y), fmaxf(c.z, c.w)));
            m3 = fmaxf(m3, fmaxf(fmaxf(d.x, d.y), fmaxf(d.z, d.w)));
        }
        float m = fmaxf(fmaxf(m0, m1), fmaxf(m2, m3));
        #pragma unroll
        for (int off = 16; off; off >>= 1)
            m = fmaxf(m, __shfl_xor_sync(0xFFFFFFFFu, m, off));
        if ((tid & 31) == 0) s_red[tid >> 5] = m;
        __syncthreads();

        // ---- Arrive: publish chunk max, bump counter, spin for sample ----
        if (tid == 0) {
            float v = s_red[0];
            #pragma unroll
            for (int r = 1; r < THREADS / 32; r++) v = fmaxf(v, s_red[r]);
            atomicMax(&g_smax[sample], ord_encode(v));
            __threadfence();
            atomicAdd(&g_arrive[sample], 1u);

            while (ld_acquire_gpu(&g_arrive[sample]) < CHUNKS)
                __nanosleep(64);
            __threadfence();
            float mx = ord_decode(g_smax[sample]);
            float sm = softplus_accurate(mx);   // = max(softplus(x)), monotone
            s_scale = (sm > EPS) ? (1.0f / sm) : 1.0f;
        }
        __syncthreads();
        const float scale = s_scale;
        const float scale_ln2 = scale * LN2;

        // ---- Pass 2: softplus * scale from SMEM, streaming store ----
        #pragma unroll
        for (int i = 0; i < 8; i++) {
            float4 v = stage[i * THREADS + tid];
            float4 r;
            r.x = softplus_scaled(v.x, scale, scale_ln2);
            r.y = softplus_scaled(v.y, scale, scale_ln2);
            r.z = softplus_scaled(v.z, scale, scale_ln2);
            r.w = softplus_scaled(v.w, scale, scale_ln2);
            __stcs(&o[i * THREADS + tid], r);
        }
        __syncthreads();   // protect s_scale / stage before next iteration

        // ---- Leave: last chunk out resets the sample's slots ----
        if (tid == 0) {
            unsigned old = atomicAdd(&g_leave[sample], 1u);
            if (old == CHUNKS - 1) {
                g_smax[sample] = 0u;
                g_arrive[sample] = 0u;
                __threadfence();
                g_leave[sample] = 0u;   // reset-complete marker for next replay
            }
        }
    }
}

extern "C" void kernel_launch(void* const* d_in, const int* in_sizes, int n_in,
                              void* d_out, int out_size) {
    const float* x = (const float*)d_in[0];
    float* out = (float*)d_out;
    int samples = in_sizes[0] / SAMPLE_ELEMS;       // 128
    int total_work = samples * CHUNKS;              // 4096
    persist_kernel<<<GRID, THREADS, SMEM_BYTES>>>(x, out, total_work);
}

// round 13
// speedup vs baseline: 1.0766x; 1.0766x over previous
#include <cuda_runtime.h>
#include <cstdint>
#include <math.h>

// x [128, 1, 512, 512] fp32.
//   pred = softplus(x); m = max over sample; out = (m > 1e-8) ? pred/m : pred.
// softplus monotone => m = softplus(max(x)).
//
// R13 = R12 (persistent, SMEM-staged, L2-bypass: 268 MB LTS instead of the
// 402 MB that capped every earlier design at ~58us) + depth-2 pipeline to
// hide the per-sample spin that cost R12 ~20us: each iteration runs
// pass1(next work item) BEFORE waiting on the current item's sample, so
// round-k stragglers finish during pass1(k+1). 512 thr, 2x32KB buffers,
// 3 CTAs/SM (48 warps, 75% occ), GRID=444.

#define SAMPLES 128
#define SAMPLE_ELEMS (512 * 512)            // 262144
#define CHUNKS 32                           // chunks per sample
#define CHUNK_N4 (SAMPLE_ELEMS / CHUNKS / 4)  // 2048 float4 = 32 KB
#define THREADS 512                         // 4 float4 per thread per buffer
#define NWARPS (THREADS / 32)               // 16
#define GRID 444                            // 148 SMs * 3 CTAs
#define SMEM_BYTES (2 * CHUNK_N4 * 16)      // 65536
#define EPS 1e-8f
#define LOG2E 1.4426950408889634f
#define LN2   0.6931471805599453f

__device__ unsigned g_smax[SAMPLES];        // ordered-uint max; 0 = "empty"
__device__ unsigned g_arrive[SAMPLES];      // arrivals
__device__ unsigned g_leave[SAMPLES];       // departures (self-reset)

__device__ __forceinline__ unsigned ord_encode(float f) {
    unsigned u = __float_as_uint(f);
    return (u >> 31) ? ~u : (u | 0x80000000u);
}
__device__ __forceinline__ float ord_decode(unsigned u) {
    return __uint_as_float((u >> 31) ? (u ^ 0x80000000u) : ~u);
}
__device__ __forceinline__ float softplus_accurate(float x) {
    return fmaxf(x, 0.0f) + log1pf(__expf(-fabsf(x)));
}
__device__ __forceinline__ float ex2f(float x) {
    float r; asm("ex2.approx.ftz.f32 %0, %1;" : "=f"(r) : "f"(x)); return r;
}
__device__ __forceinline__ float lg2f(float x) {
    float r; asm("lg2.approx.ftz.f32 %0, %1;" : "=f"(r) : "f"(x)); return r;
}
__device__ __forceinline__ float softplus_scaled(float x, float scale, float scale_ln2) {
    float t = ex2f(-LOG2E * fabsf(x));      // e^(-|x|)
    float l = lg2f(1.0f + t);               // log2(1 + e^-|x|)
    return fmaf(scale, fmaxf(x, 0.0f), scale_ln2 * l);
}
__device__ __forceinline__ unsigned ld_acquire_gpu(const unsigned* p) {
    unsigned v;
    asm volatile("ld.acquire.gpu.u32 %0, [%1];" : "=r"(v) : "l"(p));
    return v;
}

// Pass 1 for work item w into buf: stream chunk to SMEM, publish chunk max,
// bump the sample's arrive counter. Ends with the CTA fully "arrived" for w.
__device__ __forceinline__ void pass1(const float* __restrict__ x, int w,
                                      float4* buf, float* s_red, int tid) {
    const float4* __restrict__ xin =
        reinterpret_cast<const float4*>(x) + (size_t)w * CHUNK_N4;
    float4 a = __ldcs(&xin[tid]);
    float4 b = __ldcs(&xin[tid + THREADS]);
    float4 c = __ldcs(&xin[tid + 2 * THREADS]);
    float4 d = __ldcs(&xin[tid + 3 * THREADS]);
    buf[tid] = a;
    buf[tid + THREADS] = b;
    buf[tid + 2 * THREADS] = c;
    buf[tid + 3 * THREADS] = d;
    float m0 = fmaxf(fmaxf(a.x, a.y), fmaxf(a.z, a.w));
    float m1 = fmaxf(fmaxf(b.x, b.y), fmaxf(b.z, b.w));
    float m2 = fmaxf(fmaxf(c.x, c.y), fmaxf(c.z, c.w));
    float m3 = fmaxf(fmaxf(d.x, d.y), fmaxf(d.z, d.w));
    float m = fmaxf(fmaxf(m0, m1), fmaxf(m2, m3));
    #pragma unroll
    for (int off = 16; off; off >>= 1)
        m = fmaxf(m, __shfl_xor_sync(0xFFFFFFFFu, m, off));
    if ((tid & 31) == 0) s_red[tid >> 5] = m;
    __syncthreads();
    if (tid == 0) {
        float v = s_red[0];
        #pragma unroll
        for (int r = 1; r < NWARPS; r++) v = fmaxf(v, s_red[r]);
        atomicMax(&g_smax[w >> 5], ord_encode(v));
        __threadfence();
        atomicAdd(&g_arrive[w >> 5], 1u);
    }
}

// Wait for sample of w, then pass 2 from buf. Leaves counters self-reset.
__device__ __forceinline__ void pass2(float* __restrict__ out, int w,
                                      const float4* buf, float* s_scale, int tid) {
    const int sample = w >> 5;
    if (tid == 0) {
        while (ld_acquire_gpu(&g_arrive[sample]) < CHUNKS)
            __nanosleep(32);
        __threadfence();
        float mx = ord_decode(g_smax[sample]);
        float sm = softplus_accurate(mx);   // = max(softplus(x)), monotone
        *s_scale = (sm > EPS) ? (1.0f / sm) : 1.0f;
    }
    __syncthreads();
    const float scale = *s_scale;
    const float scale_ln2 = scale * LN2;

    float4* __restrict__ o = reinterpret_cast<float4*>(out) + (size_t)w * CHUNK_N4;
    #pragma unroll
    for (int i = 0; i < 4; i++) {
        float4 v = buf[i * THREADS + tid];
        float4 r;
        r.x = softplus_scaled(v.x, scale, scale_ln2);
        r.y = softplus_scaled(v.y, scale, scale_ln2);
        r.z = softplus_scaled(v.z, scale, scale_ln2);
        r.w = softplus_scaled(v.w, scale, scale_ln2);
        __stcs(&o[i * THREADS + tid], r);
    }

    if (tid == 0) {
        unsigned old = atomicAdd(&g_leave[sample], 1u);
        if (old == CHUNKS - 1) {            // last chunk out resets the sample
            g_smax[sample] = 0u;
            g_arrive[sample] = 0u;
            __threadfence();
            g_leave[sample] = 0u;
        }
    }
}

__global__ __launch_bounds__(THREADS, 3)
void persist_kernel(const float* __restrict__ x, float* __restrict__ out,
                    int total_work) {
    extern __shared__ float4 smem[];        // 2 buffers of CHUNK_N4
    __shared__ float s_red[NWARPS];
    __shared__ float s_scale;

    const int tid = threadIdx.x;
    int w = blockIdx.x;
    if (w >= total_work) return;

    int b = 0;
    pass1(x, w, smem, s_red, tid);          // prologue (includes syncthreads)

    while (true) {
        int wn = w + GRID;
        if (wn < total_work)
            pass1(x, wn, smem + (b ^ 1) * CHUNK_N4, s_red, tid);  // overlap spin

        pass2(out, w, smem + b * CHUNK_N4, &s_scale, tid);
        __syncthreads();                    // buf[b] + s_scale reuse guard

        if (wn >= total_work) break;
        w = wn;
        b ^= 1;
    }
}

extern "C" void kernel_launch(void* const* d_in, const int* in_sizes, int n_in,
                              void* d_out, int out_size) {
    const float* x = (const float*)d_in[0];
    float* out = (float*)d_out;
    static bool attr_set = false;
    if (!attr_set) {
        cudaFuncSetAttribute(persist_kernel,
                             cudaFuncAttributeMaxDynamicSharedMemorySize,
                             SMEM_BYTES);
        attr_set = true;
    }
    int samples = in_sizes[0] / SAMPLE_ELEMS;       // 128
    int total_work = samples * CHUNKS;              // 4096
    persist_kernel<<<GRID, THREADS, SMEM_BYTES>>>(x, out, total_work);
}